// round 1
// baseline (speedup 1.0000x reference)
#include <cuda_runtime.h>

namespace {

constexpr int H  = 64;
constexpr int Fd = 8;
constexpr int G  = 4 * H;   // 256 gate rows
constexpr int Tn = 512;
constexpr int Pn = 64;
constexpr int NB = 8;       // batch rows per CTA
constexpr int NT = 512;     // threads per CTA

__device__ __forceinline__ float sigf(float x) {
    return 1.0f / (1.0f + __expf(-x));
}
__device__ __forceinline__ float tanh_fast(float x) {
    // tanh(x) = 2*sigmoid(2x) - 1 ; __expf rel err ~1e-6, fine for 1e-3 gate
    return 2.0f / (1.0f + __expf(-2.0f * x)) - 1.0f;
}

// Compute 4 gate accumulators (one per local batch row) for gate row j.
__device__ __forceinline__ void gate_mm(
    const float4 w4[16], const float4 wi4[2], float bias,
    const float sh[NB][H], const float sx[NB][Fd],
    int bbase, float acc[4])
{
    acc[0] = bias; acc[1] = bias; acc[2] = bias; acc[3] = bias;
#pragma unroll
    for (int kc = 0; kc < 16; kc++) {
        float4 w  = w4[kc];
        float4 h0 = *(const float4*)&sh[bbase + 0][kc * 4];
        float4 h1 = *(const float4*)&sh[bbase + 1][kc * 4];
        float4 h2 = *(const float4*)&sh[bbase + 2][kc * 4];
        float4 h3 = *(const float4*)&sh[bbase + 3][kc * 4];
        acc[0] = fmaf(w.x, h0.x, fmaf(w.y, h0.y, fmaf(w.z, h0.z, fmaf(w.w, h0.w, acc[0]))));
        acc[1] = fmaf(w.x, h1.x, fmaf(w.y, h1.y, fmaf(w.z, h1.z, fmaf(w.w, h1.w, acc[1]))));
        acc[2] = fmaf(w.x, h2.x, fmaf(w.y, h2.y, fmaf(w.z, h2.z, fmaf(w.w, h2.w, acc[2]))));
        acc[3] = fmaf(w.x, h3.x, fmaf(w.y, h3.y, fmaf(w.z, h3.z, fmaf(w.w, h3.w, acc[3]))));
    }
#pragma unroll
    for (int kc = 0; kc < 2; kc++) {
        float4 w  = wi4[kc];
        float4 x0 = *(const float4*)&sx[bbase + 0][kc * 4];
        float4 x1 = *(const float4*)&sx[bbase + 1][kc * 4];
        float4 x2 = *(const float4*)&sx[bbase + 2][kc * 4];
        float4 x3 = *(const float4*)&sx[bbase + 3][kc * 4];
        acc[0] = fmaf(w.x, x0.x, fmaf(w.y, x0.y, fmaf(w.z, x0.z, fmaf(w.w, x0.w, acc[0]))));
        acc[1] = fmaf(w.x, x1.x, fmaf(w.y, x1.y, fmaf(w.z, x1.z, fmaf(w.w, x1.w, acc[1]))));
        acc[2] = fmaf(w.x, x2.x, fmaf(w.y, x2.y, fmaf(w.z, x2.z, fmaf(w.w, x2.w, acc[2]))));
        acc[3] = fmaf(w.x, x3.x, fmaf(w.y, x3.y, fmaf(w.z, x3.z, fmaf(w.w, x3.w, acc[3]))));
    }
}

__global__ void __launch_bounds__(NT, 1)
seq2seq_lstm_kernel(
    const float* __restrict__ input,   // [B, T, F]
    const float* __restrict__ eWih,    // [G, F]
    const float* __restrict__ eWhh,    // [G, H]
    const float* __restrict__ ebih,    // [G]
    const float* __restrict__ ebhh,    // [G]
    const float* __restrict__ dWih,    // [G, F]
    const float* __restrict__ dWhh,    // [G, H]
    const float* __restrict__ dbih,    // [G]
    const float* __restrict__ dbhh,    // [G]
    const float* __restrict__ fcW,     // [F, H]
    const float* __restrict__ fcb,     // [F]
    float* __restrict__ out)           // [B, P, F]
{
    __shared__ float sh[NB][H];        // hidden state
    __shared__ float sg[NB][G];        // gate buffer
    __shared__ float sx[NB][Fd];       // current input
    __shared__ float sfcW[Fd][H];
    __shared__ float sfcb[Fd];

    const int tid   = threadIdx.x;
    const int b0    = blockIdx.x * NB;
    const int j     = tid & (G - 1);       // gate row this thread owns
    const int bbase = (tid >> 8) * 4;      // which 4 batch rows (replica)
    const int ub    = tid >> 6;            // update-phase batch row (0..7)
    const int uu    = tid & (H - 1);       // update-phase hidden unit

    // fc weights into shared (F*H == NT exactly)
    sfcW[tid >> 6][tid & 63] = fcW[tid];
    if (tid < Fd) sfcb[tid] = fcb[tid];

    // init state
    sh[ub][uu]  = 0.0f;
    float creg  = 0.0f;

    // ---- encoder weights into registers ----
    float4 w4[16];
    float4 wi4[2];
#pragma unroll
    for (int k = 0; k < 16; k++) w4[k] = __ldg((const float4*)(eWhh + j * H) + k);
    wi4[0] = __ldg((const float4*)(eWih + j * Fd));
    wi4[1] = __ldg((const float4*)(eWih + j * Fd) + 1);
    float bias = ebih[j] + ebhh[j];

    const float* xbase = input + (size_t)b0 * Tn * Fd;

    // =================== encoder: T steps ===================
    for (int t = 0; t < Tn; t++) {
        if (tid < NB * Fd) {
            int b = tid >> 3, f = tid & 7;
            sx[b][f] = xbase[(size_t)b * Tn * Fd + t * Fd + f];
        }
        __syncthreads();   // x stored; previous h update visible

        float acc[4];
        gate_mm(w4, wi4, bias, sh, sx, bbase, acc);
        sg[bbase + 0][j] = acc[0];
        sg[bbase + 1][j] = acc[1];
        sg[bbase + 2][j] = acc[2];
        sg[bbase + 3][j] = acc[3];
        __syncthreads();   // gates complete

        float gi = sg[ub][uu];
        float gf = sg[ub][H + uu];
        float gg = sg[ub][2 * H + uu];
        float go = sg[ub][3 * H + uu];
        creg = sigf(gf) * creg + sigf(gi) * tanh_fast(gg);
        sh[ub][uu] = sigf(go) * tanh_fast(creg);
        // next iteration's first __syncthreads orders this write
    }

    // ---- decoder weights into registers ----
#pragma unroll
    for (int k = 0; k < 16; k++) w4[k] = __ldg((const float4*)(dWhh + j * H) + k);
    wi4[0] = __ldg((const float4*)(dWih + j * Fd));
    wi4[1] = __ldg((const float4*)(dWih + j * Fd) + 1);
    bias = dbih[j] + dbhh[j];
    __syncthreads();  // final encoder h visible; sx still holds input[:, T-1, :] == x_last

    // =================== decoder: P steps ===================
    for (int p = 0; p < Pn; p++) {
        float acc[4];
        gate_mm(w4, wi4, bias, sh, sx, bbase, acc);
        sg[bbase + 0][j] = acc[0];
        sg[bbase + 1][j] = acc[1];
        sg[bbase + 2][j] = acc[2];
        sg[bbase + 3][j] = acc[3];
        __syncthreads();   // gates complete

        float gi = sg[ub][uu];
        float gf = sg[ub][H + uu];
        float gg = sg[ub][2 * H + uu];
        float go = sg[ub][3 * H + uu];
        creg = sigf(gf) * creg + sigf(gi) * tanh_fast(gg);
        sh[ub][uu] = sigf(go) * tanh_fast(creg);
        __syncthreads();   // h update complete

        // fc projection: pred = h @ fcW^T + fcb ; feeds next step and output
        if (tid < NB * Fd) {
            int b = tid >> 3, f = tid & 7;
            float a = sfcb[f];
#pragma unroll
            for (int u = 0; u < H; u++) a = fmaf(sh[b][u], sfcW[f][u], a);
            out[((size_t)(b0 + b) * Pn + p) * Fd + f] = a;
            sx[b][f] = a;
        }
        __syncthreads();   // pred (next x) visible to everyone
    }
}

} // anonymous namespace

extern "C" void kernel_launch(void* const* d_in, const int* in_sizes, int n_in,
                              void* d_out, int out_size)
{
    const float* input = (const float*)d_in[0];
    const float* eWih  = (const float*)d_in[1];
    const float* eWhh  = (const float*)d_in[2];
    const float* ebih  = (const float*)d_in[3];
    const float* ebhh  = (const float*)d_in[4];
    const float* dWih  = (const float*)d_in[5];
    const float* dWhh  = (const float*)d_in[6];
    const float* dbih  = (const float*)d_in[7];
    const float* dbhh  = (const float*)d_in[8];
    const float* fcW   = (const float*)d_in[9];
    const float* fcb   = (const float*)d_in[10];
    float* out = (float*)d_out;

    const int B = 1024;
    seq2seq_lstm_kernel<<<B / NB, NT>>>(input, eWih, eWhh, ebih, ebhh,
                                        dWih, dWhh, dbih, dbhh, fcW, fcb, out);
}

// round 2
// speedup vs baseline: 1.2209x; 1.2209x over previous
#include <cuda_runtime.h>

namespace {

constexpr int H  = 64;
constexpr int Fd = 8;
constexpr int G  = 4 * H;   // 256 gate rows
constexpr int Tn = 512;
constexpr int Pn = 64;
constexpr int NB = 4;       // batch rows per CTA
constexpr int NT = 256;     // threads per CTA (one per gate row)

using u64 = unsigned long long;

__device__ __forceinline__ u64 ffma2(u64 a, u64 b, u64 c) {
    u64 d;
    asm("fma.rn.f32x2 %0, %1, %2, %3;" : "=l"(d) : "l"(a), "l"(b), "l"(c));
    return d;
}
__device__ __forceinline__ u64 pack2(float lo, float hi) {
    u64 d;
    asm("mov.b64 %0, {%1, %2};" : "=l"(d) : "f"(lo), "f"(hi));
    return d;
}
__device__ __forceinline__ float hsum2(u64 v) {
    float lo, hi;
    asm("mov.b64 {%0, %1}, %2;" : "=f"(lo), "=f"(hi) : "l"(v));
    return lo + hi;
}

__device__ __forceinline__ float sigf(float x) {
    return 1.0f / (1.0f + __expf(-x));
}
__device__ __forceinline__ float tanh_fast(float x) {
    return 2.0f / (1.0f + __expf(-2.0f * x)) - 1.0f;
}

// gates for row j, all 4 batch rows; k vectorized in f32x2 pairs.
__device__ __forceinline__ void gate_mm(
    const u64 w2[32], const u64 wi2[4], u64 binit,
    const float sh[NB][H], const float sx[NB][Fd], u64 acc[NB])
{
    acc[0] = binit; acc[1] = binit; acc[2] = binit; acc[3] = binit;
#pragma unroll
    for (int kc = 0; kc < 16; kc++) {
        u64 wlo = w2[2 * kc], whi = w2[2 * kc + 1];
#pragma unroll
        for (int b = 0; b < NB; b++) {
            ulonglong2 hv = *(const ulonglong2*)&sh[b][kc * 4];
            acc[b] = ffma2(wlo, hv.x, acc[b]);
            acc[b] = ffma2(whi, hv.y, acc[b]);
        }
    }
#pragma unroll
    for (int kc = 0; kc < 2; kc++) {
        u64 wlo = wi2[2 * kc], whi = wi2[2 * kc + 1];
#pragma unroll
        for (int b = 0; b < NB; b++) {
            ulonglong2 xv = *(const ulonglong2*)&sx[b][kc * 4];
            acc[b] = ffma2(wlo, xv.x, acc[b]);
            acc[b] = ffma2(whi, xv.y, acc[b]);
        }
    }
}

__device__ __forceinline__ void load_w(
    const float* __restrict__ Whh, const float* __restrict__ Wih,
    const float* __restrict__ bih, const float* __restrict__ bhh,
    int j, u64 w2[32], u64 wi2[4], u64& binit)
{
    const ulonglong2* wp = (const ulonglong2*)(Whh + j * H);
#pragma unroll
    for (int k = 0; k < 16; k++) {
        ulonglong2 v = __ldg(wp + k);
        w2[2 * k] = v.x; w2[2 * k + 1] = v.y;
    }
    const ulonglong2* wi = (const ulonglong2*)(Wih + j * Fd);
#pragma unroll
    for (int k = 0; k < 2; k++) {
        ulonglong2 v = __ldg(wi + k);
        wi2[2 * k] = v.x; wi2[2 * k + 1] = v.y;
    }
    binit = pack2(bih[j] + bhh[j], 0.0f);
}

__global__ void __launch_bounds__(NT, 2)
seq2seq_lstm_kernel(
    const float* __restrict__ input,   // [B, T, F]
    const float* __restrict__ eWih,    // [G, F]
    const float* __restrict__ eWhh,    // [G, H]
    const float* __restrict__ ebih,    // [G]
    const float* __restrict__ ebhh,    // [G]
    const float* __restrict__ dWih,    // [G, F]
    const float* __restrict__ dWhh,    // [G, H]
    const float* __restrict__ dbih,    // [G]
    const float* __restrict__ dbhh,    // [G]
    const float* __restrict__ fcW,     // [F, H]
    const float* __restrict__ fcb,     // [F]
    float* __restrict__ out)           // [B, P, F]
{
    __shared__ float sh[NB][H];        // hidden state
    __shared__ float sg[NB][G];        // gate buffer
    __shared__ float sx[NB][Fd];       // current input
    __shared__ float sfcW[Fd][H];
    __shared__ float sfcb[Fd];

    const int tid = threadIdx.x;
    const int b0  = blockIdx.x * NB;
    const int j   = tid;               // gate row this thread owns
    const int ub  = tid >> 6;          // update-phase batch row (0..3)
    const int uu  = tid & (H - 1);     // update-phase hidden unit

    // fc weights into shared (F*H == 512, 2 per thread)
    ((float*)sfcW)[tid]       = fcW[tid];
    ((float*)sfcW)[tid + NT]  = fcW[tid + NT];
    if (tid < Fd) sfcb[tid] = fcb[tid];

    // init state
    ((float*)sh)[tid] = 0.0f;
    float creg = 0.0f;

    // encoder weights into registers (k-pair packed)
    u64 w2[32], wi2[4], binit;
    load_w(eWhh, eWih, ebih, ebhh, j, w2, wi2, binit);

    const bool xth = tid < NB * Fd;
    const int  xb  = tid >> 3;         // batch row for x/fc duty
    const int  xf  = tid & 7;          // feature
    const float* xptr = input + ((size_t)(b0 + xb) * Tn + 0) * Fd + xf;
    float xreg = xth ? xptr[0] : 0.0f;

    // =================== encoder: T steps ===================
    for (int t = 0; t < Tn; t++) {
        if (xth) sx[xb][xf] = xreg;
        __syncthreads();   // x(t) stored; h(t-1) visible
        if (xth && t + 1 < Tn) xreg = xptr[(size_t)(t + 1) * Fd];  // prefetch

        u64 acc[NB];
        gate_mm(w2, wi2, binit, sh, sx, acc);
        sg[0][j] = hsum2(acc[0]);
        sg[1][j] = hsum2(acc[1]);
        sg[2][j] = hsum2(acc[2]);
        sg[3][j] = hsum2(acc[3]);
        __syncthreads();   // gates complete

        float gi = sg[ub][uu];
        float gf = sg[ub][H + uu];
        float gg = sg[ub][2 * H + uu];
        float go = sg[ub][3 * H + uu];
        creg = sigf(gf) * creg + sigf(gi) * tanh_fast(gg);
        sh[ub][uu] = sigf(go) * tanh_fast(creg);
        // next iteration's first __syncthreads orders this write
    }

    // decoder weights
    load_w(dWhh, dWih, dbih, dbhh, j, w2, wi2, binit);
    __syncthreads();  // final encoder h visible; sx holds x[:, T-1, :]

    // =================== decoder: P steps ===================
    for (int p = 0; p < Pn; p++) {
        u64 acc[NB];
        gate_mm(w2, wi2, binit, sh, sx, acc);
        sg[0][j] = hsum2(acc[0]);
        sg[1][j] = hsum2(acc[1]);
        sg[2][j] = hsum2(acc[2]);
        sg[3][j] = hsum2(acc[3]);
        __syncthreads();   // gates complete

        float gi = sg[ub][uu];
        float gf = sg[ub][H + uu];
        float gg = sg[ub][2 * H + uu];
        float go = sg[ub][3 * H + uu];
        creg = sigf(gf) * creg + sigf(gi) * tanh_fast(gg);
        sh[ub][uu] = sigf(go) * tanh_fast(creg);
        __syncthreads();   // h update complete

        if (xth) {  // fc projection: pred = h @ fcW^T + fcb
            float a = sfcb[xf];
#pragma unroll
            for (int u = 0; u < H; u++) a = fmaf(sh[xb][u], sfcW[xf][u], a);
            out[((size_t)(b0 + xb) * Pn + p) * Fd + xf] = a;
            sx[xb][xf] = a;
        }
        __syncthreads();   // pred (next x) visible
    }
}

} // anonymous namespace

extern "C" void kernel_launch(void* const* d_in, const int* in_sizes, int n_in,
                              void* d_out, int out_size)
{
    const float* input = (const float*)d_in[0];
    const float* eWih  = (const float*)d_in[1];
    const float* eWhh  = (const float*)d_in[2];
    const float* ebih  = (const float*)d_in[3];
    const float* ebhh  = (const float*)d_in[4];
    const float* dWih  = (const float*)d_in[5];
    const float* dWhh  = (const float*)d_in[6];
    const float* dbih  = (const float*)d_in[7];
    const float* dbhh  = (const float*)d_in[8];
    const float* fcW   = (const float*)d_in[9];
    const float* fcb   = (const float*)d_in[10];
    float* out = (float*)d_out;

    const int B = 1024;
    seq2seq_lstm_kernel<<<B / NB, NT>>>(input, eWih, eWhh, ebih, ebhh,
                                        dWih, dWhh, dbih, dbhh, fcW, fcb, out);
}